// round 1
// baseline (speedup 1.0000x reference)
#include <cuda_runtime.h>

// ============================================================================
// QuantizedBlock: quantized transformer block (B=4, N=1024, C=1024, HID=4096,
// H=16, D=64). All qz() fake-quant ops are exact fixed-point: values are
// int8 * 2^-frac, so fp32 GEMM accumulation is bit-exact vs. the reference.
// ============================================================================

#define DEV __device__ __forceinline__

// qz(x, 8, F): round-half-even (rintf), clip to [-128,127], rescale.
template <int F>
DEV float qz(float x) {
    const float s   = (F == 4) ? 16.0f : 128.0f;
    const float inv = (F == 4) ? 0.0625f : 0.0078125f;
    float f = rintf(x * s);
    f = fminf(fmaxf(f, -128.0f), 127.0f);
    return f * inv;
}

// ---------------------------------------------------------------------------
// Scratch (device globals — no allocation allowed in kernel_launch)
// ---------------------------------------------------------------------------
#define TOK 4096   // B*N
__device__ float g_h  [4096L * 1024];        // affine output
__device__ float g_q  [4096L * 1024];        // q projection
__device__ float g_kv [4096L * 2048];        // kv projection
__device__ float g_s  [64L * 1024 * 1024];   // attention scores [B*H, N, N]
__device__ float g_z  [4096L * 1024];        // attention context
__device__ float g_x1 [4096L * 1024];        // residual after attention
__device__ float g_mid[4096L * 4096];        // fc1 output
__device__ float g_t  [4096L * 1024];        // proj / fc2 output

// ---------------------------------------------------------------------------
// Generic quantized GEMM:  C[m,n] = sum_k qz<FA>(A[m,k]) * qz<FB>(B[.,.])
//   BKC = true : B is [n][k] row-major, k contiguous (weights / K tiles)
//   BKC = false: B is [k][n], n contiguous with k-stride ldb  (V tiles)
// Batch over blockIdx.z = b*16 + h with separate (b, h) strides.
// EPI: 0 none; 1 +qz7(bias); 2 qz4(relu(+qz7(bias))); 3 qz4(0.125*acc)
// ---------------------------------------------------------------------------
template <int BM, int BN, int TM, int TN, int FA, int FB, bool BKC, int EPI>
__global__ void __launch_bounds__(256)
gemm_q(const float* __restrict__ A, const float* __restrict__ B,
       const float* __restrict__ bias, float* __restrict__ C,
       int K, long long lda, long long ldb, long long ldc,
       long long sAb, long long sAh, long long sBb, long long sBh,
       long long sCb, long long sCh)
{
    constexpr int BK = 16;
    const int bb = blockIdx.z >> 4;
    const int hh = blockIdx.z & 15;
    A += bb * sAb + hh * sAh;
    B += bb * sBb + hh * sBh;
    C += bb * sCb + hh * sCh;

    __shared__ float As[BK][BM + 4];
    __shared__ float Bs[BK][BN + 4];

    const int tid = threadIdx.x;
    const int tx  = tid % (BN / TN);
    const int ty  = tid / (BN / TN);
    const long long m0 = (long long)blockIdx.y * BM;
    const long long n0 = (long long)blockIdx.x * BN;

    float acc[TM][TN];
#pragma unroll
    for (int i = 0; i < TM; i++)
#pragma unroll
        for (int j = 0; j < TN; j++) acc[i][j] = 0.0f;

    for (int kb = 0; kb < K; kb += BK) {
        // ---- load A tile (row-major, k contiguous) ----
#pragma unroll
        for (int v = 0; v < (BM * BK) / (256 * 4); v++) {
            int idx = (tid + v * 256) * 4;
            int r = idx / BK, kk = idx % BK;
            float4 t = *reinterpret_cast<const float4*>(A + (m0 + r) * lda + kb + kk);
            As[kk + 0][r] = qz<FA>(t.x);
            As[kk + 1][r] = qz<FA>(t.y);
            As[kk + 2][r] = qz<FA>(t.z);
            As[kk + 3][r] = qz<FA>(t.w);
        }
        // ---- load B tile ----
#pragma unroll
        for (int v = 0; v < (BN * BK) / (256 * 4); v++) {
            int idx = (tid + v * 256) * 4;
            if (BKC) {
                int r = idx / BK, kk = idx % BK;
                float4 t = *reinterpret_cast<const float4*>(B + (n0 + r) * ldb + kb + kk);
                Bs[kk + 0][r] = qz<FB>(t.x);
                Bs[kk + 1][r] = qz<FB>(t.y);
                Bs[kk + 2][r] = qz<FB>(t.z);
                Bs[kk + 3][r] = qz<FB>(t.w);
            } else {
                int kk = idx / BN, nn = idx % BN;
                float4 t = *reinterpret_cast<const float4*>(B + (long long)(kb + kk) * ldb + n0 + nn);
                float4 o;
                o.x = qz<FB>(t.x); o.y = qz<FB>(t.y);
                o.z = qz<FB>(t.z); o.w = qz<FB>(t.w);
                *reinterpret_cast<float4*>(&Bs[kk][nn]) = o;
            }
        }
        __syncthreads();

#pragma unroll
        for (int k = 0; k < BK; k++) {
            float a[TM], b[TN];
#pragma unroll
            for (int ii = 0; ii < TM / 4; ii++) {
                float4 t = *reinterpret_cast<const float4*>(&As[k][ty * TM + ii * 4]);
                a[ii * 4 + 0] = t.x; a[ii * 4 + 1] = t.y;
                a[ii * 4 + 2] = t.z; a[ii * 4 + 3] = t.w;
            }
#pragma unroll
            for (int jj = 0; jj < TN / 4; jj++) {
                float4 t = *reinterpret_cast<const float4*>(&Bs[k][tx * TN + jj * 4]);
                b[jj * 4 + 0] = t.x; b[jj * 4 + 1] = t.y;
                b[jj * 4 + 2] = t.z; b[jj * 4 + 3] = t.w;
            }
#pragma unroll
            for (int i = 0; i < TM; i++)
#pragma unroll
                for (int j = 0; j < TN; j++)
                    acc[i][j] += a[i] * b[j];
        }
        __syncthreads();
    }

#pragma unroll
    for (int i = 0; i < TM; i++) {
        long long m = m0 + ty * TM + i;
#pragma unroll
        for (int j = 0; j < TN; j++) {
            long long n = n0 + tx * TN + j;
            float y = acc[i][j];
            if (EPI == 1)      y += qz<7>(bias[n]);
            else if (EPI == 2) y = qz<4>(fmaxf(y + qz<7>(bias[n]), 0.0f));
            else if (EPI == 3) y = qz<4>(y * 0.125f);
            C[m * ldc + n] = y;
        }
    }
}

// ---------------------------------------------------------------------------
// Softmax over rows of 1024 + qz(.,8,7). One block (256 thr) per row.
// ---------------------------------------------------------------------------
__global__ void __launch_bounds__(256) softmax_qz7_kernel(float* __restrict__ S)
{
    float* row = S + (long long)blockIdx.x * 1024;
    const int t = threadIdx.x;
    float4 v = reinterpret_cast<const float4*>(row)[t];

    float m = fmaxf(fmaxf(v.x, v.y), fmaxf(v.z, v.w));
#pragma unroll
    for (int o = 16; o > 0; o >>= 1) m = fmaxf(m, __shfl_xor_sync(0xffffffffu, m, o));
    __shared__ float red[8];
    if ((t & 31) == 0) red[t >> 5] = m;
    __syncthreads();
    m = red[0];
#pragma unroll
    for (int w = 1; w < 8; w++) m = fmaxf(m, red[w]);

    float e0 = expf(v.x - m), e1 = expf(v.y - m);
    float e2 = expf(v.z - m), e3 = expf(v.w - m);
    float s = (e0 + e1) + (e2 + e3);
#pragma unroll
    for (int o = 16; o > 0; o >>= 1) s += __shfl_xor_sync(0xffffffffu, s, o);
    __syncthreads();
    if ((t & 31) == 0) red[t >> 5] = s;
    __syncthreads();
    s = 0.0f;
#pragma unroll
    for (int w = 0; w < 8; w++) s += red[w];

    float4 o;
    o.x = qz<7>(e0 / s); o.y = qz<7>(e1 / s);
    o.z = qz<7>(e2 / s); o.w = qz<7>(e3 / s);
    reinterpret_cast<float4*>(row)[t] = o;
}

// ---------------------------------------------------------------------------
// Elementwise: affine (fixed_affine) and residual add, float4-vectorized.
// ---------------------------------------------------------------------------
__global__ void __launch_bounds__(256) affine_kernel(
    const float* __restrict__ X, const float* __restrict__ w,
    const float* __restrict__ b, float* __restrict__ O)
{
    long long i = (long long)blockIdx.x * 256 + threadIdx.x;
    const float qw = qz<4>(w[0]);
    const float qb = qz<4>(b[0]);
    float4 v = reinterpret_cast<const float4*>(X)[i];
    float4 o;
    o.x = qz<4>(qz<4>(v.x) * qw) + qb;
    o.y = qz<4>(qz<4>(v.y) * qw) + qb;
    o.z = qz<4>(qz<4>(v.z) * qw) + qb;
    o.w = qz<4>(qz<4>(v.w) * qw) + qb;
    reinterpret_cast<float4*>(O)[i] = o;
}

__global__ void __launch_bounds__(256) add_q4_kernel(
    const float* __restrict__ Aa, const float* __restrict__ Bb, float* __restrict__ O)
{
    long long i = (long long)blockIdx.x * 256 + threadIdx.x;
    float4 a = reinterpret_cast<const float4*>(Aa)[i];
    float4 b = reinterpret_cast<const float4*>(Bb)[i];
    float4 o;
    o.x = qz<4>(a.x) + qz<4>(b.x);
    o.y = qz<4>(a.y) + qz<4>(b.y);
    o.z = qz<4>(a.z) + qz<4>(b.z);
    o.w = qz<4>(a.w) + qz<4>(b.w);
    reinterpret_cast<float4*>(O)[i] = o;
}

// ---------------------------------------------------------------------------
// Launcher
// ---------------------------------------------------------------------------
extern "C" void kernel_launch(void* const* d_in, const int* in_sizes, int n_in,
                              void* d_out, int out_size)
{
    const float* x      = (const float*)d_in[0];
    const float* q_w    = (const float*)d_in[1];
    const float* kv_w   = (const float*)d_in[2];
    const float* proj_w = (const float*)d_in[3];
    const float* proj_b = (const float*)d_in[4];
    const float* fc1_w  = (const float*)d_in[5];
    const float* fc1_b  = (const float*)d_in[6];
    const float* fc2_w  = (const float*)d_in[7];
    const float* fc2_b  = (const float*)d_in[8];
    const float* aff1_w = (const float*)d_in[9];
    const float* aff1_b = (const float*)d_in[10];
    const float* aff2_w = (const float*)d_in[11];
    const float* aff2_b = (const float*)d_in[12];
    float* out = (float*)d_out;

    float *h, *q, *kv, *s, *z, *x1, *mid, *t;
    cudaGetSymbolAddress((void**)&h,   g_h);
    cudaGetSymbolAddress((void**)&q,   g_q);
    cudaGetSymbolAddress((void**)&kv,  g_kv);
    cudaGetSymbolAddress((void**)&s,   g_s);
    cudaGetSymbolAddress((void**)&z,   g_z);
    cudaGetSymbolAddress((void**)&x1,  g_x1);
    cudaGetSymbolAddress((void**)&mid, g_mid);
    cudaGetSymbolAddress((void**)&t,   g_t);

    const long long Z = 0;
    const int EW_BLOCKS = (TOK * 1024) / (4 * 256);  // 4096

    // 1. h = affine(x, aff1)
    affine_kernel<<<EW_BLOCKS, 256>>>(x, aff1_w, aff1_b, h);

    // 2. q = qlinear(h, q_w)           [4096,1024]
    gemm_q<128,128,8,8, 4,7, true, 0><<<dim3(8, 32, 1), 256>>>(
        h, q_w, nullptr, q, 1024, 1024, 1024, 1024, Z, Z, Z, Z, Z, Z);

    // 3. kv = qlinear(h, kv_w)         [4096,2048]
    gemm_q<128,128,8,8, 4,7, true, 0><<<dim3(16, 32, 1), 256>>>(
        h, kv_w, nullptr, kv, 1024, 1024, 1024, 2048, Z, Z, Z, Z, Z, Z);

    // 4. scores = qz4(0.125 * qz4(q) @ qz4(k)^T), batched over (b,h)
    gemm_q<128,128,8,8, 4,4, true, 3><<<dim3(8, 8, 64), 256>>>(
        q, kv, nullptr, s, 64, 1024, 2048, 1024,
        1024LL * 1024, 64LL,            // A (q): b-stride, h-stride
        1024LL * 2048, 64LL,            // B (k)
        16LL * 1024 * 1024, 1024LL * 1024);  // C (scores)

    // 5. softmax + qz7, per row
    softmax_qz7_kernel<<<64 * 1024, 256>>>(s);

    // 6. z = P @ qz4(v)   (B tile is [k][n] with k-stride 2048)
    gemm_q<64,64,4,4, 7,4, false, 0><<<dim3(1, 16, 64), 256>>>(
        s, kv + 1024, nullptr, z, 1024, 1024, 2048, 1024,
        16LL * 1024 * 1024, 1024LL * 1024,  // A (scores)
        1024LL * 2048, 64LL,                // B (v)
        1024LL * 1024, 64LL);               // C (z)

    // 7. t = qlinear(z, proj_w, proj_b)
    gemm_q<128,128,8,8, 4,7, true, 1><<<dim3(8, 32, 1), 256>>>(
        z, proj_w, proj_b, t, 1024, 1024, 1024, 1024, Z, Z, Z, Z, Z, Z);

    // 8. x1 = qz4(x) + qz4(t)
    add_q4_kernel<<<EW_BLOCKS, 256>>>(x, t, x1);

    // 9. h = affine(x1, aff2)
    affine_kernel<<<EW_BLOCKS, 256>>>(x1, aff2_w, aff2_b, h);

    // 10. mid = qz4(relu(qlinear(h, fc1_w, fc1_b)))   [4096,4096]
    gemm_q<128,128,8,8, 4,7, true, 2><<<dim3(32, 32, 1), 256>>>(
        h, fc1_w, fc1_b, mid, 1024, 1024, 1024, 4096, Z, Z, Z, Z, Z, Z);

    // 11. t = qlinear(mid, fc2_w, fc2_b)              [4096,1024]
    gemm_q<128,128,8,8, 4,7, true, 1><<<dim3(8, 32, 1), 256>>>(
        mid, fc2_w, fc2_b, t, 4096, 4096, 4096, 1024, Z, Z, Z, Z, Z, Z);

    // 12. out = qz4(x1) + qz4(t)
    add_q4_kernel<<<EW_BLOCKS, 256>>>(x1, t, out);
}

// round 2
// speedup vs baseline: 3.7235x; 3.7235x over previous
#include <cuda_runtime.h>
#include <cuda_bf16.h>
#include <cstdint>

// ============================================================================
// QuantizedBlock on tensor cores. All qz() values are int8 * 2^-f -> exact in
// bf16; fp32 accumulation of the integer-valued products is bit-exact.
// Pipeline: pre-quantize operands to bf16, run bf16 mma.sync GEMMs with fused
// quantized epilogues, keep all intermediates in bf16.
// ============================================================================

#define DEV __device__ __forceinline__

DEV float qz4f(float x) {
    float f = rintf(x * 16.0f);
    f = fminf(fmaxf(f, -128.0f), 127.0f);
    return f * 0.0625f;
}
DEV float qz7f(float x) {
    float f = rintf(x * 128.0f);
    f = fminf(fmaxf(f, -128.0f), 127.0f);
    return f * 0.0078125f;
}

DEV uint32_t pack2(float x, float y) {
    __nv_bfloat162 t;
    t.x = __float2bfloat16(x); t.y = __float2bfloat16(y);
    return *reinterpret_cast<uint32_t*>(&t);
}
DEV void unpack2(uint32_t u, float& x, float& y) {
    __nv_bfloat162 t = *reinterpret_cast<__nv_bfloat162*>(&u);
    x = __bfloat162float(t.x); y = __bfloat162float(t.y);
}

// ---------------------------------------------------------------------------
// Scratch (bf16 everywhere; no allocation allowed in kernel_launch)
// ---------------------------------------------------------------------------
__device__ __nv_bfloat16 g_hq  [4096L * 1024];   // quantized affine output
__device__ __nv_bfloat16 g_qq  [4096L * 1024];   // qz4(q)
__device__ __nv_bfloat16 g_kvq [4096L * 2048];   // qz4(kv)
__device__ __nv_bfloat16 g_s   [64L * 1024 * 1024]; // scores / probs
__device__ __nv_bfloat16 g_zq  [4096L * 1024];   // qz4(attn context)
__device__ __nv_bfloat16 g_pj  [4096L * 1024];   // qz4(proj out)
__device__ __nv_bfloat16 g_x1  [4096L * 1024];   // residual 1 (exact)
__device__ __nv_bfloat16 g_mid [4096L * 4096];   // qz4(relu(fc1))
__device__ __nv_bfloat16 g_f2  [4096L * 1024];   // qz4(fc2 out)
__device__ __nv_bfloat16 g_wq  [1024L * 1024];
__device__ __nv_bfloat16 g_wkv [2048L * 1024];
__device__ __nv_bfloat16 g_wpj [1024L * 1024];
__device__ __nv_bfloat16 g_wf1 [4096L * 1024];
__device__ __nv_bfloat16 g_wf2 [1024L * 4096];

// ---------------------------------------------------------------------------
// PTX wrappers
// ---------------------------------------------------------------------------
DEV void ldsm_x4(uint32_t& r0, uint32_t& r1, uint32_t& r2, uint32_t& r3, uint32_t addr) {
    asm volatile("ldmatrix.sync.aligned.m8n8.x4.shared.b16 {%0,%1,%2,%3}, [%4];\n"
                 : "=r"(r0), "=r"(r1), "=r"(r2), "=r"(r3) : "r"(addr));
}
DEV void ldsm_x4_t(uint32_t& r0, uint32_t& r1, uint32_t& r2, uint32_t& r3, uint32_t addr) {
    asm volatile("ldmatrix.sync.aligned.m8n8.x4.trans.shared.b16 {%0,%1,%2,%3}, [%4];\n"
                 : "=r"(r0), "=r"(r1), "=r"(r2), "=r"(r3) : "r"(addr));
}
DEV void mma16816(float* c, const uint32_t* a, const uint32_t* b) {
    asm volatile(
        "mma.sync.aligned.m16n8k16.row.col.f32.bf16.bf16.f32 "
        "{%0,%1,%2,%3}, {%4,%5,%6,%7}, {%8,%9}, {%0,%1,%2,%3};\n"
        : "+f"(c[0]), "+f"(c[1]), "+f"(c[2]), "+f"(c[3])
        : "r"(a[0]), "r"(a[1]), "r"(a[2]), "r"(a[3]), "r"(b[0]), "r"(b[1]));
}

DEV uint32_t sw128(uint32_t byte) { return byte ^ ((byte >> 3) & 0x70); }

// ---------------------------------------------------------------------------
// bf16 tensor-core GEMM:  C[m,n] = sum_k A[m,k]*B[n,k]   (both k-contiguous)
// BTRANS: B stored [k][n] with n contiguous (V in PV) -> ldmatrix.trans path.
// EPI: 0 qz4(acc); 1 qz4(acc*0.125); 2 qz4(acc+qz7(bias)); 3 qz4(relu(acc+qz7(bias)))
// Batched over blockIdx.z = b*16+h via separate strides.
// ---------------------------------------------------------------------------
template <int BM, int BN, bool BTRANS, int EPI>
__global__ void __launch_bounds__(256)
mma_gemm(const __nv_bfloat16* __restrict__ A, const __nv_bfloat16* __restrict__ B,
         const float* __restrict__ bias, __nv_bfloat16* __restrict__ C, int K,
         long long lda, long long ldb, long long ldc,
         long long sAb, long long sAh, long long sBb, long long sBh,
         long long sCb, long long sCh)
{
    constexpr int BK = 64;
    constexpr int MF = (BM / 4) / 16;   // m16 frags per warp (2)
    constexpr int NF = (BN / 2) / 8;    // n8 frags per warp (8 or 4)

    const int bb = blockIdx.z >> 4, hh = blockIdx.z & 15;
    A += bb * sAb + hh * sAh;
    B += bb * sBb + hh * sBh;
    C += bb * sCb + hh * sCh;

    __shared__ __align__(128) __nv_bfloat16 smA[BM * BK];
    __shared__ __align__(128) __nv_bfloat16 smB[BTRANS ? BK * BN : BN * BK];

    const int tid = threadIdx.x;
    const int warp = tid >> 5, lane = tid & 31;
    const int wm0 = (warp >> 1) * (BM / 4);
    const int wn0 = (warp & 1) * (BN / 2);
    const long long m0 = (long long)blockIdx.y * BM;
    const long long n0 = (long long)blockIdx.x * BN;

    const uint32_t sA = (uint32_t)__cvta_generic_to_shared(smA);
    const uint32_t sB = (uint32_t)__cvta_generic_to_shared(smB);

    float acc[MF][NF][4];
#pragma unroll
    for (int i = 0; i < MF; i++)
#pragma unroll
        for (int j = 0; j < NF; j++)
#pragma unroll
            for (int p = 0; p < 4; p++) acc[i][j][p] = 0.0f;

    for (int kb = 0; kb < K; kb += BK) {
        // ---- stage A tile [BM][64] (128B rows, SW128) ----
#pragma unroll
        for (int v = 0; v < BM / 32; v++) {
            int idx = tid + v * 256;
            int r = idx >> 3, c = idx & 7;
            uint32_t byte = sw128(r * 128 + c * 16);
            *(uint4*)((char*)smA + byte) =
                *(const uint4*)(A + (m0 + r) * lda + kb + c * 8);
        }
        // ---- stage B tile ----
        if (!BTRANS) {
#pragma unroll
            for (int v = 0; v < BN / 32; v++) {
                int idx = tid + v * 256;
                int r = idx >> 3, c = idx & 7;
                uint32_t byte = sw128(r * 128 + c * 16);
                *(uint4*)((char*)smB + byte) =
                    *(const uint4*)(B + (n0 + r) * ldb + kb + c * 8);
            }
        } else {
#pragma unroll
            for (int v = 0; v < (BK * BN) / (8 * 256); v++) {
                int idx = tid + v * 256;
                int r = idx >> 3, c = idx & 7;
                uint32_t byte = sw128(r * 128 + c * 16);
                *(uint4*)((char*)smB + byte) =
                    *(const uint4*)(B + (kb + r) * ldb + n0 + c * 8);
            }
        }
        __syncthreads();

#pragma unroll
        for (int ks = 0; ks < BK / 16; ks++) {
            uint32_t a[MF][4];
#pragma unroll
            for (int mf = 0; mf < MF; mf++) {
                int r = wm0 + mf * 16 + (lane & 15);
                uint32_t byte = sw128(r * 128 + ks * 32 + (lane >> 4) * 16);
                ldsm_x4(a[mf][0], a[mf][1], a[mf][2], a[mf][3], sA + byte);
            }
            uint32_t b[NF][2];
#pragma unroll
            for (int np = 0; np < NF / 2; np++) {
                uint32_t r0, r1, r2, r3;
                if (!BTRANS) {
                    int n = wn0 + np * 16 + (lane >> 4) * 8 + (lane & 7);
                    uint32_t byte = sw128(n * 128 + ks * 32 + ((lane >> 3) & 1) * 16);
                    ldsm_x4(r0, r1, r2, r3, sB + byte);
                } else {
                    int r = ks * 16 + (lane & 15);
                    int n = wn0 + np * 16 + (lane >> 4) * 8;
                    uint32_t byte = sw128(r * 128 + n * 2);
                    ldsm_x4_t(r0, r1, r2, r3, sB + byte);
                }
                b[np * 2][0] = r0; b[np * 2][1] = r1;
                b[np * 2 + 1][0] = r2; b[np * 2 + 1][1] = r3;
            }
#pragma unroll
            for (int mf = 0; mf < MF; mf++)
#pragma unroll
                for (int nf = 0; nf < NF; nf++)
                    mma16816(acc[mf][nf], a[mf], b[nf]);
        }
        __syncthreads();
    }

    // ---- epilogue: quantize, write bf16 ----
    const int g = lane >> 2, tg = lane & 3;
#pragma unroll
    for (int mf = 0; mf < MF; mf++) {
        long long r0 = m0 + wm0 + mf * 16 + g;
#pragma unroll
        for (int nf = 0; nf < NF; nf++) {
            long long cc = n0 + wn0 + nf * 8 + 2 * tg;
            float y0 = acc[mf][nf][0], y1 = acc[mf][nf][1];
            float y2 = acc[mf][nf][2], y3 = acc[mf][nf][3];
            if (EPI == 1) { y0 *= 0.125f; y1 *= 0.125f; y2 *= 0.125f; y3 *= 0.125f; }
            if (EPI == 2 || EPI == 3) {
                float qb0 = qz7f(bias[cc]), qb1 = qz7f(bias[cc + 1]);
                y0 += qb0; y1 += qb1; y2 += qb0; y3 += qb1;
            }
            if (EPI == 3) {
                y0 = fmaxf(y0, 0.0f); y1 = fmaxf(y1, 0.0f);
                y2 = fmaxf(y2, 0.0f); y3 = fmaxf(y3, 0.0f);
            }
            y0 = qz4f(y0); y1 = qz4f(y1); y2 = qz4f(y2); y3 = qz4f(y3);
            *(uint32_t*)(C + r0 * ldc + cc) = pack2(y0, y1);
            *(uint32_t*)(C + (r0 + 8) * ldc + cc) = pack2(y2, y3);
        }
    }
}

// ---------------------------------------------------------------------------
// Softmax over bf16 rows of 1024 + qz7. One block per row.
// ---------------------------------------------------------------------------
__global__ void __launch_bounds__(256) softmax_q7_kernel(__nv_bfloat16* __restrict__ S)
{
    __nv_bfloat16* row = S + (long long)blockIdx.x * 1024;
    const int t = threadIdx.x;
    uint2 u = reinterpret_cast<const uint2*>(row)[t];
    float v0, v1, v2, v3;
    unpack2(u.x, v0, v1);
    unpack2(u.y, v2, v3);

    float m = fmaxf(fmaxf(v0, v1), fmaxf(v2, v3));
#pragma unroll
    for (int o = 16; o > 0; o >>= 1) m = fmaxf(m, __shfl_xor_sync(0xffffffffu, m, o));
    __shared__ float red[8];
    if ((t & 31) == 0) red[t >> 5] = m;
    __syncthreads();
    m = red[0];
#pragma unroll
    for (int w = 1; w < 8; w++) m = fmaxf(m, red[w]);

    float e0 = expf(v0 - m), e1 = expf(v1 - m);
    float e2 = expf(v2 - m), e3 = expf(v3 - m);
    float s = (e0 + e1) + (e2 + e3);
#pragma unroll
    for (int o = 16; o > 0; o >>= 1) s += __shfl_xor_sync(0xffffffffu, s, o);
    __syncthreads();
    if ((t & 31) == 0) red[t >> 5] = s;
    __syncthreads();
    s = 0.0f;
#pragma unroll
    for (int w = 0; w < 8; w++) s += red[w];
    float inv = 1.0f / s;

    uint2 o;
    o.x = pack2(qz7f(e0 * inv), qz7f(e1 * inv));
    o.y = pack2(qz7f(e2 * inv), qz7f(e3 * inv));
    reinterpret_cast<uint2*>(row)[t] = o;
}

// ---------------------------------------------------------------------------
// Elementwise kernels
// ---------------------------------------------------------------------------
__global__ void __launch_bounds__(256) quantw_kernel(
    const float* __restrict__ W, __nv_bfloat16* __restrict__ O)
{
    long long i = (long long)blockIdx.x * 256 + threadIdx.x;
    float4 v = reinterpret_cast<const float4*>(W)[i];
    uint2 o;
    o.x = pack2(qz7f(v.x), qz7f(v.y));
    o.y = pack2(qz7f(v.z), qz7f(v.w));
    reinterpret_cast<uint2*>(O)[i] = o;
}

// affine from fp32 input: out = qz4( qz4(qz4(x)*qw) + qb )
__global__ void __launch_bounds__(256) affine_f32_kernel(
    const float* __restrict__ X, const float* __restrict__ w,
    const float* __restrict__ b, __nv_bfloat16* __restrict__ O)
{
    long long i = (long long)blockIdx.x * 256 + threadIdx.x;
    const float qw = qz4f(w[0]);
    const float qb = qz4f(b[0]);
    float4 v = reinterpret_cast<const float4*>(X)[i];
    float y0 = qz4f(qz4f(qz4f(v.x) * qw) + qb);
    float y1 = qz4f(qz4f(qz4f(v.y) * qw) + qb);
    float y2 = qz4f(qz4f(qz4f(v.z) * qw) + qb);
    float y3 = qz4f(qz4f(qz4f(v.w) * qw) + qb);
    uint2 o; o.x = pack2(y0, y1); o.y = pack2(y2, y3);
    reinterpret_cast<uint2*>(O)[i] = o;
}

// affine from bf16 input
__global__ void __launch_bounds__(256) affine_bf16_kernel(
    const __nv_bfloat16* __restrict__ X, const float* __restrict__ w,
    const float* __restrict__ b, __nv_bfloat16* __restrict__ O)
{
    long long i = (long long)blockIdx.x * 256 + threadIdx.x;
    const float qw = qz4f(w[0]);
    const float qb = qz4f(b[0]);
    uint2 u = reinterpret_cast<const uint2*>(X)[i];
    float v0, v1, v2, v3;
    unpack2(u.x, v0, v1); unpack2(u.y, v2, v3);
    uint2 o;
    o.x = pack2(qz4f(qz4f(qz4f(v0) * qw) + qb), qz4f(qz4f(qz4f(v1) * qw) + qb));
    o.y = pack2(qz4f(qz4f(qz4f(v2) * qw) + qb), qz4f(qz4f(qz4f(v3) * qw) + qb));
    reinterpret_cast<uint2*>(O)[i] = o;
}

// x1 = qz4(x_f32) + pj (pj already qz4'ed) -> bf16 (exact: step 2^-4, |.|<16)
__global__ void __launch_bounds__(256) add1_kernel(
    const float* __restrict__ X, const __nv_bfloat16* __restrict__ P,
    __nv_bfloat16* __restrict__ O)
{
    long long i = (long long)blockIdx.x * 256 + threadIdx.x;
    float4 x = reinterpret_cast<const float4*>(X)[i];
    uint2 p = reinterpret_cast<const uint2*>(P)[i];
    float p0, p1, p2, p3;
    unpack2(p.x, p0, p1); unpack2(p.y, p2, p3);
    uint2 o;
    o.x = pack2(qz4f(x.x) + p0, qz4f(x.y) + p1);
    o.y = pack2(qz4f(x.z) + p2, qz4f(x.w) + p3);
    reinterpret_cast<uint2*>(O)[i] = o;
}

// out_f32 = qz4(x1) + f2 (f2 already qz4'ed)
__global__ void __launch_bounds__(256) add2_kernel(
    const __nv_bfloat16* __restrict__ X1, const __nv_bfloat16* __restrict__ F,
    float* __restrict__ O)
{
    long long i = (long long)blockIdx.x * 256 + threadIdx.x;
    uint2 a = reinterpret_cast<const uint2*>(X1)[i];
    uint2 f = reinterpret_cast<const uint2*>(F)[i];
    float a0, a1, a2, a3, f0, f1, f2v, f3;
    unpack2(a.x, a0, a1); unpack2(a.y, a2, a3);
    unpack2(f.x, f0, f1); unpack2(f.y, f2v, f3);
    float4 o;
    o.x = qz4f(a0) + f0; o.y = qz4f(a1) + f1;
    o.z = qz4f(a2) + f2v; o.w = qz4f(a3) + f3;
    reinterpret_cast<float4*>(O)[i] = o;
}

// ---------------------------------------------------------------------------
// Launcher
// ---------------------------------------------------------------------------
extern "C" void kernel_launch(void* const* d_in, const int* in_sizes, int n_in,
                              void* d_out, int out_size)
{
    const float* x      = (const float*)d_in[0];
    const float* q_w    = (const float*)d_in[1];
    const float* kv_w   = (const float*)d_in[2];
    const float* proj_w = (const float*)d_in[3];
    const float* proj_b = (const float*)d_in[4];
    const float* fc1_w  = (const float*)d_in[5];
    const float* fc1_b  = (const float*)d_in[6];
    const float* fc2_w  = (const float*)d_in[7];
    const float* fc2_b  = (const float*)d_in[8];
    const float* aff1_w = (const float*)d_in[9];
    const float* aff1_b = (const float*)d_in[10];
    const float* aff2_w = (const float*)d_in[11];
    const float* aff2_b = (const float*)d_in[12];
    float* out = (float*)d_out;

    __nv_bfloat16 *hq, *qq, *kvq, *s, *zq, *pj, *x1, *mid, *f2;
    __nv_bfloat16 *wq, *wkv, *wpj, *wf1, *wf2;
    cudaGetSymbolAddress((void**)&hq,  g_hq);
    cudaGetSymbolAddress((void**)&qq,  g_qq);
    cudaGetSymbolAddress((void**)&kvq, g_kvq);
    cudaGetSymbolAddress((void**)&s,   g_s);
    cudaGetSymbolAddress((void**)&zq,  g_zq);
    cudaGetSymbolAddress((void**)&pj,  g_pj);
    cudaGetSymbolAddress((void**)&x1,  g_x1);
    cudaGetSymbolAddress((void**)&mid, g_mid);
    cudaGetSymbolAddress((void**)&f2,  g_f2);
    cudaGetSymbolAddress((void**)&wq,  g_wq);
    cudaGetSymbolAddress((void**)&wkv, g_wkv);
    cudaGetSymbolAddress((void**)&wpj, g_wpj);
    cudaGetSymbolAddress((void**)&wf1, g_wf1);
    cudaGetSymbolAddress((void**)&wf2, g_wf2);

    const long long Z = 0;
    const long long M1 = 1024LL * 1024;

    // weights -> qz7 bf16
    quantw_kernel<<<1024, 256>>>(q_w, wq);
    quantw_kernel<<<2048, 256>>>(kv_w, wkv);
    quantw_kernel<<<1024, 256>>>(proj_w, wpj);
    quantw_kernel<<<4096, 256>>>(fc1_w, wf1);
    quantw_kernel<<<4096, 256>>>(fc2_w, wf2);

    // 1. hq = qz4(affine(x, aff1))
    affine_f32_kernel<<<4096, 256>>>(x, aff1_w, aff1_b, hq);

    // 2. qq = qz4(hq @ wq^T)
    mma_gemm<128, 128, false, 0><<<dim3(8, 32, 1), 256>>>(
        hq, wq, nullptr, qq, 1024, 1024, 1024, 1024, Z, Z, Z, Z, Z, Z);

    // 3. kvq = qz4(hq @ wkv^T)
    mma_gemm<128, 128, false, 0><<<dim3(16, 32, 1), 256>>>(
        hq, wkv, nullptr, kvq, 1024, 1024, 1024, 2048, Z, Z, Z, Z, Z, Z);

    // 4. scores = qz4(0.125 * qq @ kq^T), batched over (b,h)
    mma_gemm<128, 128, false, 1><<<dim3(8, 8, 64), 256>>>(
        qq, kvq, nullptr, s, 64, 1024, 2048, 1024,
        1024LL * 1024, 64LL,
        1024LL * 2048, 64LL,
        16LL * M1, M1);

    // 5. softmax + qz7 (in place)
    softmax_q7_kernel<<<64 * 1024, 256>>>(s);

    // 6. zq = qz4(P @ vq)  (V is [k][n] with n contiguous -> trans path)
    mma_gemm<128, 64, true, 0><<<dim3(1, 8, 64), 256>>>(
        s, kvq + 1024, nullptr, zq, 1024, 1024, 2048, 1024,
        16LL * M1, M1,
        1024LL * 2048, 64LL,
        1024LL * 1024, 64LL);

    // 7. pj = qz4(zq @ wpj^T + qz7(proj_b))
    mma_gemm<128, 128, false, 2><<<dim3(8, 32, 1), 256>>>(
        zq, wpj, proj_b, pj, 1024, 1024, 1024, 1024, Z, Z, Z, Z, Z, Z);

    // 8. x1 = qz4(x) + pj
    add1_kernel<<<4096, 256>>>(x, pj, x1);

    // 9. hq = qz4(affine(x1, aff2))
    affine_bf16_kernel<<<4096, 256>>>(x1, aff2_w, aff2_b, hq);

    // 10. mid = qz4(relu(hq @ wf1^T + qz7(fc1_b)))
    mma_gemm<128, 128, false, 3><<<dim3(32, 32, 1), 256>>>(
        hq, wf1, fc1_b, mid, 1024, 1024, 1024, 4096, Z, Z, Z, Z, Z, Z);

    // 11. f2 = qz4(mid @ wf2^T + qz7(fc2_b))
    mma_gemm<128, 128, false, 2><<<dim3(8, 32, 1), 256>>>(
        mid, wf2, fc2_b, f2, 4096, 4096, 4096, 1024, Z, Z, Z, Z, Z, Z);

    // 12. out = qz4(x1) + f2
    add2_kernel<<<4096, 256>>>(x1, f2, out);
}

// round 3
// speedup vs baseline: 5.9016x; 1.5850x over previous
#include <cuda_runtime.h>
#include <cuda_bf16.h>
#include <cstdint>

#define DEV __device__ __forceinline__
typedef __nv_bfloat16 bf16;

DEV float qz4f(float x) {
    float f = rintf(x * 16.0f);
    f = fminf(fmaxf(f, -128.0f), 127.0f);
    return f * 0.0625f;
}
DEV float qz7f(float x) {
    float f = rintf(x * 128.0f);
    f = fminf(fmaxf(f, -128.0f), 127.0f);
    return f * 0.0078125f;
}
DEV uint32_t pack2(float x, float y) {
    __nv_bfloat162 t;
    t.x = __float2bfloat16(x); t.y = __float2bfloat16(y);
    return *reinterpret_cast<uint32_t*>(&t);
}
DEV void unpack2(uint32_t u, float& x, float& y) {
    __nv_bfloat162 t = *reinterpret_cast<__nv_bfloat162*>(&u);
    x = __bfloat162float(t.x); y = __bfloat162float(t.y);
}

// ---------------------------------------------------------------------------
// Scratch
// ---------------------------------------------------------------------------
__device__ bf16 g_hq  [4096L * 1024];
__device__ bf16 g_qq  [4096L * 1024];
__device__ bf16 g_kvq [4096L * 2048];
__device__ bf16 g_zq  [4096L * 1024];
__device__ bf16 g_pj  [4096L * 1024];
__device__ bf16 g_x1  [4096L * 1024];
__device__ bf16 g_mid [4096L * 4096];
__device__ bf16 g_f2  [4096L * 1024];
__device__ bf16 g_wq  [1024L * 1024];
__device__ bf16 g_wkv [2048L * 1024];
__device__ bf16 g_wpj [1024L * 1024];
__device__ bf16 g_wf1 [4096L * 1024];
__device__ bf16 g_wf2 [1024L * 4096];

// ---------------------------------------------------------------------------
// PTX wrappers
// ---------------------------------------------------------------------------
DEV void ldsm_x4(uint32_t& r0, uint32_t& r1, uint32_t& r2, uint32_t& r3, uint32_t addr) {
    asm volatile("ldmatrix.sync.aligned.m8n8.x4.shared.b16 {%0,%1,%2,%3}, [%4];\n"
                 : "=r"(r0), "=r"(r1), "=r"(r2), "=r"(r3) : "r"(addr));
}
DEV void ldsm_x4_t(uint32_t& r0, uint32_t& r1, uint32_t& r2, uint32_t& r3, uint32_t addr) {
    asm volatile("ldmatrix.sync.aligned.m8n8.x4.trans.shared.b16 {%0,%1,%2,%3}, [%4];\n"
                 : "=r"(r0), "=r"(r1), "=r"(r2), "=r"(r3) : "r"(addr));
}
DEV void mma16816(float* c, const uint32_t* a, const uint32_t* b) {
    asm volatile(
        "mma.sync.aligned.m16n8k16.row.col.f32.bf16.bf16.f32 "
        "{%0,%1,%2,%3}, {%4,%5,%6,%7}, {%8,%9}, {%0,%1,%2,%3};\n"
        : "+f"(c[0]), "+f"(c[1]), "+f"(c[2]), "+f"(c[3])
        : "r"(a[0]), "r"(a[1]), "r"(a[2]), "r"(a[3]), "r"(b[0]), "r"(b[1]));
}
DEV uint32_t sw128(uint32_t byte) { return byte ^ ((byte >> 3) & 0x70); }

DEV void cpasync16(uint32_t dst, const void* src) {
    asm volatile("cp.async.cg.shared.global [%0], [%1], 16;\n" :: "r"(dst), "l"(src));
}
DEV void cpcommit() { asm volatile("cp.async.commit_group;\n" ::: "memory"); }
template <int N> DEV void cpwait() { asm volatile("cp.async.wait_group %0;\n" :: "n"(N) : "memory"); }

// ---------------------------------------------------------------------------
// Pipelined weight GEMM: C[m,n] = epi( sum_k A[m,k]*B[n,k] )
// A [M][K] k-contig, B [N][K] k-contig, C [M][N]. BM=BN=128, BK=64, 2 stages.
// EPI: 0 qz4(acc); 2 qz4(acc+qz7(bias)); 3 qz4(relu(acc+qz7(bias)))
// Dynamic smem: 64 KB.
// ---------------------------------------------------------------------------
template <int EPI>
__global__ void __launch_bounds__(256)
gemm_pipe(const bf16* __restrict__ A, const bf16* __restrict__ B,
          const float* __restrict__ bias, bf16* __restrict__ C, int N, int K)
{
    extern __shared__ char smem_raw[];
    const int tid = threadIdx.x, warp = tid >> 5, lane = tid & 31;
    const int wm = (warp >> 1) * 32, wn = (warp & 1) * 64;
    const long long m0 = (long long)blockIdx.y * 128;
    const long long n0 = (long long)blockIdx.x * 128;
    const uint32_t sbase = (uint32_t)__cvta_generic_to_shared(smem_raw);

    const bf16* Ap = A + m0 * K;
    const bf16* Bp = B + n0 * K;

    float acc[2][8][4];
#pragma unroll
    for (int i = 0; i < 2; i++)
#pragma unroll
        for (int j = 0; j < 8; j++)
#pragma unroll
            for (int p = 0; p < 4; p++) acc[i][j][p] = 0.0f;

    auto loadtile = [&](int s, int kt) {
        uint32_t sa = sbase + s * 32768;
        uint32_t sb = sa + 16384;
        const bf16* Ak = Ap + (long long)kt * 64;
        const bf16* Bk = Bp + (long long)kt * 64;
#pragma unroll
        for (int v = 0; v < 4; v++) {
            int idx = tid + v * 256;
            int r = idx >> 3, c = idx & 7;
            uint32_t off = sw128(r * 128 + c * 16);
            cpasync16(sa + off, Ak + (long long)r * K + c * 8);
            cpasync16(sb + off, Bk + (long long)r * K + c * 8);
        }
    };

    const int nt = K >> 6;
    loadtile(0, 0); cpcommit();

    for (int t = 0; t < nt; t++) {
        if (t + 1 < nt) { loadtile((t + 1) & 1, t + 1); cpcommit(); cpwait<1>(); }
        else            { cpwait<0>(); }
        __syncthreads();
        uint32_t sa = sbase + (t & 1) * 32768;
        uint32_t sb = sa + 16384;
#pragma unroll
        for (int ks = 0; ks < 4; ks++) {
            uint32_t a[2][4];
#pragma unroll
            for (int mf = 0; mf < 2; mf++) {
                int r = wm + mf * 16 + (lane & 15);
                ldsm_x4(a[mf][0], a[mf][1], a[mf][2], a[mf][3],
                        sa + sw128(r * 128 + ks * 32 + (lane >> 4) * 16));
            }
            uint32_t bfr[8][2];
#pragma unroll
            for (int np = 0; np < 4; np++) {
                uint32_t r0, r1, r2, r3;
                int n = wn + np * 16 + (lane >> 4) * 8 + (lane & 7);
                ldsm_x4(r0, r1, r2, r3,
                        sb + sw128(n * 128 + ks * 32 + ((lane >> 3) & 1) * 16));
                bfr[np * 2][0] = r0; bfr[np * 2][1] = r1;
                bfr[np * 2 + 1][0] = r2; bfr[np * 2 + 1][1] = r3;
            }
#pragma unroll
            for (int mf = 0; mf < 2; mf++)
#pragma unroll
                for (int nf = 0; nf < 8; nf++)
                    mma16816(acc[mf][nf], a[mf], bfr[nf]);
        }
        __syncthreads();
    }

    const int g = lane >> 2, tg = lane & 3;
#pragma unroll
    for (int mf = 0; mf < 2; mf++) {
        long long r0 = m0 + wm + mf * 16 + g;
#pragma unroll
        for (int nf = 0; nf < 8; nf++) {
            long long cc = n0 + wn + nf * 8 + 2 * tg;
            float y0 = acc[mf][nf][0], y1 = acc[mf][nf][1];
            float y2 = acc[mf][nf][2], y3 = acc[mf][nf][3];
            if (EPI == 2 || EPI == 3) {
                float qb0 = qz7f(__ldg(bias + cc)), qb1 = qz7f(__ldg(bias + cc + 1));
                y0 += qb0; y1 += qb1; y2 += qb0; y3 += qb1;
            }
            if (EPI == 3) {
                y0 = fmaxf(y0, 0.0f); y1 = fmaxf(y1, 0.0f);
                y2 = fmaxf(y2, 0.0f); y3 = fmaxf(y3, 0.0f);
            }
            y0 = qz4f(y0); y1 = qz4f(y1); y2 = qz4f(y2); y3 = qz4f(y3);
            *(uint32_t*)(C + r0 * N + cc) = pack2(y0, y1);
            *(uint32_t*)(C + (r0 + 8) * N + cc) = pack2(y2, y3);
        }
    }
}

// ---------------------------------------------------------------------------
// Fused attention: per (b,h, 128-row q-tile):
//   pass1: S = qz4(0.125 * qq@kq^T) streamed in 128-key chunks -> row max m,
//          online-rescaled row sum l of exp(S - m).
//   pass2: recompute S in 64-key chunks, p = qz7(exp(S-m)/l), feed C-frags
//          repacked as A-frags into PV mma with V via ldmatrix.trans.
// Writes zq = qz4(z). 256 threads, 8 warps x 16 q-rows.
// ---------------------------------------------------------------------------
__global__ void __launch_bounds__(256)
attn_fused(const bf16* __restrict__ qq, const bf16* __restrict__ kvq,
           bf16* __restrict__ zq)
{
    __shared__ __align__(128) char smem_raw[49152];   // 16KB Q + 2x16KB stages
    const int tid = threadIdx.x, warp = tid >> 5, lane = tid & 31;
    const int bh = blockIdx.y;
    const int b = bh >> 4, h = bh & 15;
    const long long qrow0 = (long long)b * 1024 + (long long)blockIdx.x * 128;

    const bf16* Qp = qq + qrow0 * 1024 + h * 64;
    const bf16* Kp = kvq + (long long)b * 1024 * 2048 + h * 64;
    const bf16* Vp = Kp + 1024;

    const uint32_t sbase = (uint32_t)__cvta_generic_to_shared(smem_raw);
    const uint32_t sQ = sbase;
    const uint32_t sS = sbase + 16384;
    const int wm = warp * 16;

    // load Q tile [128][64]
#pragma unroll
    for (int v = 0; v < 4; v++) {
        int idx = tid + v * 256;
        int r = idx >> 3, c = idx & 7;
        cpasync16(sQ + sw128(r * 128 + c * 16), Qp + (long long)r * 1024 + c * 8);
    }

    auto loadK128 = [&](int s, int c) {
        uint32_t base = sS + s * 16384;
#pragma unroll
        for (int v = 0; v < 4; v++) {
            int idx = tid + v * 256;
            int r = idx >> 3, cd = idx & 7;
            cpasync16(base + sw128(r * 128 + cd * 16),
                      Kp + (long long)(c * 128 + r) * 2048 + cd * 8);
        }
    };

    loadK128(0, 0); cpcommit();

    float m[2] = {-1e30f, -1e30f}, l[2] = {0.0f, 0.0f};

    // ---------------- pass 1: stats ----------------
    for (int c = 0; c < 8; c++) {
        if (c + 1 < 8) { loadK128((c + 1) & 1, c + 1); cpcommit(); cpwait<1>(); }
        else           { cpwait<0>(); }
        __syncthreads();
        uint32_t sk = sS + (c & 1) * 16384;

        float acc[16][4];
#pragma unroll
        for (int i = 0; i < 16; i++)
#pragma unroll
            for (int p = 0; p < 4; p++) acc[i][p] = 0.0f;

#pragma unroll
        for (int ks = 0; ks < 4; ks++) {
            uint32_t a[4];
            int ar = wm + (lane & 15);
            ldsm_x4(a[0], a[1], a[2], a[3],
                    sQ + sw128(ar * 128 + ks * 32 + (lane >> 4) * 16));
            uint32_t bfr[16][2];
#pragma unroll
            for (int np = 0; np < 8; np++) {
                uint32_t r0, r1, r2, r3;
                int n = np * 16 + (lane >> 4) * 8 + (lane & 7);
                ldsm_x4(r0, r1, r2, r3,
                        sk + sw128(n * 128 + ks * 32 + ((lane >> 3) & 1) * 16));
                bfr[np * 2][0] = r0; bfr[np * 2][1] = r1;
                bfr[np * 2 + 1][0] = r2; bfr[np * 2 + 1][1] = r3;
            }
#pragma unroll
            for (int nf = 0; nf < 16; nf++)
                mma16816(acc[nf], a, bfr[nf]);
        }

        // stats: rows r0 = lane>>2 (vals [0],[1]) and r0+8 (vals [2],[3])
        float mx0 = -1e30f, mx1 = -1e30f;
#pragma unroll
        for (int nf = 0; nf < 16; nf++) {
            acc[nf][0] = qz4f(acc[nf][0] * 0.125f);
            acc[nf][1] = qz4f(acc[nf][1] * 0.125f);
            acc[nf][2] = qz4f(acc[nf][2] * 0.125f);
            acc[nf][3] = qz4f(acc[nf][3] * 0.125f);
            mx0 = fmaxf(mx0, fmaxf(acc[nf][0], acc[nf][1]));
            mx1 = fmaxf(mx1, fmaxf(acc[nf][2], acc[nf][3]));
        }
        mx0 = fmaxf(mx0, __shfl_xor_sync(0xffffffffu, mx0, 1));
        mx0 = fmaxf(mx0, __shfl_xor_sync(0xffffffffu, mx0, 2));
        mx1 = fmaxf(mx1, __shfl_xor_sync(0xffffffffu, mx1, 1));
        mx1 = fmaxf(mx1, __shfl_xor_sync(0xffffffffu, mx1, 2));

        float mn0 = fmaxf(m[0], mx0), mn1 = fmaxf(m[1], mx1);
        float s0 = 0.0f, s1 = 0.0f;
#pragma unroll
        for (int nf = 0; nf < 16; nf++) {
            s0 += expf(acc[nf][0] - mn0) + expf(acc[nf][1] - mn0);
            s1 += expf(acc[nf][2] - mn1) + expf(acc[nf][3] - mn1);
        }
        s0 += __shfl_xor_sync(0xffffffffu, s0, 1);
        s0 += __shfl_xor_sync(0xffffffffu, s0, 2);
        s1 += __shfl_xor_sync(0xffffffffu, s1, 1);
        s1 += __shfl_xor_sync(0xffffffffu, s1, 2);

        l[0] = l[0] * expf(m[0] - mn0) + s0; m[0] = mn0;
        l[1] = l[1] * expf(m[1] - mn1) + s1; m[1] = mn1;
        __syncthreads();
    }

    const float linv0 = 1.0f / l[0], linv1 = 1.0f / l[1];

    // ---------------- pass 2: probs + PV ----------------
    auto loadKV64 = [&](int s, int c) {
        uint32_t base = sS + s * 16384;
#pragma unroll
        for (int v = 0; v < 2; v++) {
            int idx = tid + v * 256;
            int r = idx >> 3, cd = idx & 7;
            uint32_t off = sw128(r * 128 + cd * 16);
            cpasync16(base + off, Kp + (long long)(c * 64 + r) * 2048 + cd * 8);
            cpasync16(base + 8192 + off, Vp + (long long)(c * 64 + r) * 2048 + cd * 8);
        }
    };

    float zacc[8][4];
#pragma unroll
    for (int j = 0; j < 8; j++)
#pragma unroll
        for (int p = 0; p < 4; p++) zacc[j][p] = 0.0f;

    loadKV64(0, 0); cpcommit();

    for (int c = 0; c < 16; c++) {
        if (c + 1 < 16) { loadKV64((c + 1) & 1, c + 1); cpcommit(); cpwait<1>(); }
        else            { cpwait<0>(); }
        __syncthreads();
        uint32_t sk = sS + (c & 1) * 16384;
        uint32_t sv = sk + 8192;

        float acc[8][4];
#pragma unroll
        for (int i = 0; i < 8; i++)
#pragma unroll
            for (int p = 0; p < 4; p++) acc[i][p] = 0.0f;

#pragma unroll
        for (int ks = 0; ks < 4; ks++) {
            uint32_t a[4];
            int ar = wm + (lane & 15);
            ldsm_x4(a[0], a[1], a[2], a[3],
                    sQ + sw128(ar * 128 + ks * 32 + (lane >> 4) * 16));
            uint32_t bfr[8][2];
#pragma unroll
            for (int np = 0; np < 4; np++) {
                uint32_t r0, r1, r2, r3;
                int n = np * 16 + (lane >> 4) * 8 + (lane & 7);
                ldsm_x4(r0, r1, r2, r3,
                        sk + sw128(n * 128 + ks * 32 + ((lane >> 3) & 1) * 16));
                bfr[np * 2][0] = r0; bfr[np * 2][1] = r1;
                bfr[np * 2 + 1][0] = r2; bfr[np * 2 + 1][1] = r3;
            }
#pragma unroll
            for (int nf = 0; nf < 8; nf++)
                mma16816(acc[nf], a, bfr[nf]);
        }

        // p = qz7(exp(qz4(s*0.125) - m) / l); repack C-frags -> A-frags
        uint32_t afr[4][4];
#pragma unroll
        for (int kk = 0; kk < 4; kk++) {
            float p00 = qz7f(expf(qz4f(acc[2 * kk][0] * 0.125f) - m[0]) * linv0);
            float p01 = qz7f(expf(qz4f(acc[2 * kk][1] * 0.125f) - m[0]) * linv0);
            float p02 = qz7f(expf(qz4f(acc[2 * kk][2] * 0.125f) - m[1]) * linv1);
            float p03 = qz7f(expf(qz4f(acc[2 * kk][3] * 0.125f) - m[1]) * linv1);
            float p10 = qz7f(expf(qz4f(acc[2 * kk + 1][0] * 0.125f) - m[0]) * linv0);
            float p11 = qz7f(expf(qz4f(acc[2 * kk + 1][1] * 0.125f) - m[0]) * linv0);
            float p12 = qz7f(expf(qz4f(acc[2 * kk + 1][2] * 0.125f) - m[1]) * linv1);
            float p13 = qz7f(expf(qz4f(acc[2 * kk + 1][3] * 0.125f) - m[1]) * linv1);
            afr[kk][0] = pack2(p00, p01);
            afr[kk][1] = pack2(p02, p03);
            afr[kk][2] = pack2(p10, p11);
            afr[kk][3] = pack2(p12, p13);
        }

        // PV: z += P(16x64) @ V(64x64)
#pragma unroll
        for (int kk = 0; kk < 4; kk++) {
            uint32_t vfr[8][2];
#pragma unroll
            for (int np = 0; np < 4; np++) {
                uint32_t r0, r1, r2, r3;
                int r = kk * 16 + (lane & 15);
                int n = np * 16 + (lane >> 4) * 8;
                ldsm_x4_t(r0, r1, r2, r3, sv + sw128(r * 128 + n * 2));
                vfr[np * 2][0] = r0; vfr[np * 2][1] = r1;
                vfr[np * 2 + 1][0] = r2; vfr[np * 2 + 1][1] = r3;
            }
#pragma unroll
            for (int nf = 0; nf < 8; nf++)
                mma16816(zacc[nf], afr[kk], vfr[nf]);
        }
        __syncthreads();
    }

    // epilogue: zq = qz4(z)
    const int g = lane >> 2, tg = lane & 3;
    const long long r0 = qrow0 + wm + g;
#pragma unroll
    for (int nf = 0; nf < 8; nf++) {
        long long cc = (long long)h * 64 + nf * 8 + 2 * tg;
        *(uint32_t*)(zq + r0 * 1024 + cc) = pack2(qz4f(zacc[nf][0]), qz4f(zacc[nf][1]));
        *(uint32_t*)(zq + (r0 + 8) * 1024 + cc) = pack2(qz4f(zacc[nf][2]), qz4f(zacc[nf][3]));
    }
}

// ---------------------------------------------------------------------------
// Elementwise kernels
// ---------------------------------------------------------------------------
__global__ void __launch_bounds__(256) quantw_kernel(
    const float* __restrict__ W, bf16* __restrict__ O)
{
    long long i = (long long)blockIdx.x * 256 + threadIdx.x;
    float4 v = reinterpret_cast<const float4*>(W)[i];
    uint2 o;
    o.x = pack2(qz7f(v.x), qz7f(v.y));
    o.y = pack2(qz7f(v.z), qz7f(v.w));
    reinterpret_cast<uint2*>(O)[i] = o;
}

__global__ void __launch_bounds__(256) affine_f32_kernel(
    const float* __restrict__ X, const float* __restrict__ w,
    const float* __restrict__ b, bf16* __restrict__ O)
{
    long long i = (long long)blockIdx.x * 256 + threadIdx.x;
    const float qw = qz4f(w[0]);
    const float qb = qz4f(b[0]);
    float4 v = reinterpret_cast<const float4*>(X)[i];
    uint2 o;
    o.x = pack2(qz4f(qz4f(qz4f(v.x) * qw) + qb), qz4f(qz4f(qz4f(v.y) * qw) + qb));
    o.y = pack2(qz4f(qz4f(qz4f(v.z) * qw) + qb), qz4f(qz4f(qz4f(v.w) * qw) + qb));
    reinterpret_cast<uint2*>(O)[i] = o;
}

__global__ void __launch_bounds__(256) affine_bf16_kernel(
    const bf16* __restrict__ X, const float* __restrict__ w,
    const float* __restrict__ b, bf16* __restrict__ O)
{
    long long i = (long long)blockIdx.x * 256 + threadIdx.x;
    const float qw = qz4f(w[0]);
    const float qb = qz4f(b[0]);
    uint2 u = reinterpret_cast<const uint2*>(X)[i];
    float v0, v1, v2, v3;
    unpack2(u.x, v0, v1); unpack2(u.y, v2, v3);
    uint2 o;
    o.x = pack2(qz4f(qz4f(qz4f(v0) * qw) + qb), qz4f(qz4f(qz4f(v1) * qw) + qb));
    o.y = pack2(qz4f(qz4f(qz4f(v2) * qw) + qb), qz4f(qz4f(qz4f(v3) * qw) + qb));
    reinterpret_cast<uint2*>(O)[i] = o;
}

__global__ void __launch_bounds__(256) add1_kernel(
    const float* __restrict__ X, const bf16* __restrict__ P, bf16* __restrict__ O)
{
    long long i = (long long)blockIdx.x * 256 + threadIdx.x;
    float4 x = reinterpret_cast<const float4*>(X)[i];
    uint2 p = reinterpret_cast<const uint2*>(P)[i];
    float p0, p1, p2, p3;
    unpack2(p.x, p0, p1); unpack2(p.y, p2, p3);
    uint2 o;
    o.x = pack2(qz4f(x.x) + p0, qz4f(x.y) + p1);
    o.y = pack2(qz4f(x.z) + p2, qz4f(x.w) + p3);
    reinterpret_cast<uint2*>(O)[i] = o;
}

__global__ void __launch_bounds__(256) add2_kernel(
    const bf16* __restrict__ X1, const bf16* __restrict__ F, float* __restrict__ O)
{
    long long i = (long long)blockIdx.x * 256 + threadIdx.x;
    uint2 a = reinterpret_cast<const uint2*>(X1)[i];
    uint2 f = reinterpret_cast<const uint2*>(F)[i];
    float a0, a1, a2, a3, f0, f1, f2v, f3;
    unpack2(a.x, a0, a1); unpack2(a.y, a2, a3);
    unpack2(f.x, f0, f1); unpack2(f.y, f2v, f3);
    float4 o;
    o.x = qz4f(a0) + f0; o.y = qz4f(a1) + f1;
    o.z = qz4f(a2) + f2v; o.w = qz4f(a3) + f3;
    reinterpret_cast<float4*>(O)[i] = o;
}

// ---------------------------------------------------------------------------
// Launcher
// ---------------------------------------------------------------------------
extern "C" void kernel_launch(void* const* d_in, const int* in_sizes, int n_in,
                              void* d_out, int out_size)
{
    const float* x      = (const float*)d_in[0];
    const float* q_w    = (const float*)d_in[1];
    const float* kv_w   = (const float*)d_in[2];
    const float* proj_w = (const float*)d_in[3];
    const float* proj_b = (const float*)d_in[4];
    const float* fc1_w  = (const float*)d_in[5];
    const float* fc1_b  = (const float*)d_in[6];
    const float* fc2_w  = (const float*)d_in[7];
    const float* fc2_b  = (const float*)d_in[8];
    const float* aff1_w = (const float*)d_in[9];
    const float* aff1_b = (const float*)d_in[10];
    const float* aff2_w = (const float*)d_in[11];
    const float* aff2_b = (const float*)d_in[12];
    float* out = (float*)d_out;

    bf16 *hq, *qq, *kvq, *zq, *pj, *x1, *mid, *f2;
    bf16 *wq, *wkv, *wpj, *wf1, *wf2;
    cudaGetSymbolAddress((void**)&hq,  g_hq);
    cudaGetSymbolAddress((void**)&qq,  g_qq);
    cudaGetSymbolAddress((void**)&kvq, g_kvq);
    cudaGetSymbolAddress((void**)&zq,  g_zq);
    cudaGetSymbolAddress((void**)&pj,  g_pj);
    cudaGetSymbolAddress((void**)&x1,  g_x1);
    cudaGetSymbolAddress((void**)&mid, g_mid);
    cudaGetSymbolAddress((void**)&f2,  g_f2);
    cudaGetSymbolAddress((void**)&wq,  g_wq);
    cudaGetSymbolAddress((void**)&wkv, g_wkv);
    cudaGetSymbolAddress((void**)&wpj, g_wpj);
    cudaGetSymbolAddress((void**)&wf1, g_wf1);
    cudaGetSymbolAddress((void**)&wf2, g_wf2);

    static bool attr_done = false;
    if (!attr_done) {
        cudaFuncSetAttribute(gemm_pipe<0>, cudaFuncAttributeMaxDynamicSharedMemorySize, 65536);
        cudaFuncSetAttribute(gemm_pipe<2>, cudaFuncAttributeMaxDynamicSharedMemorySize, 65536);
        cudaFuncSetAttribute(gemm_pipe<3>, cudaFuncAttributeMaxDynamicSharedMemorySize, 65536);
        attr_done = true;
    }

    // 0: hq = qz4(affine(x, aff1))
    affine_f32_kernel<<<4096, 256>>>(x, aff1_w, aff1_b, hq);
    // 1-2: quantize q/kv weights
    quantw_kernel<<<1024, 256>>>(q_w, wq);
    quantw_kernel<<<2048, 256>>>(kv_w, wkv);
    // 3: qq = qz4(hq @ wq^T)
    gemm_pipe<0><<<dim3(8, 32), 256, 65536>>>(hq, wq, nullptr, qq, 1024, 1024);
    // 4: kvq = qz4(hq @ wkv^T)
    gemm_pipe<0><<<dim3(16, 32), 256, 65536>>>(hq, wkv, nullptr, kvq, 2048, 1024);
    // 5: fused attention (profiled launch)
    attn_fused<<<dim3(8, 64), 256>>>(qq, kvq, zq);
    // 6: proj weights
    quantw_kernel<<<1024, 256>>>(proj_w, wpj);
    // 7: pj = qz4(zq @ wpj^T + qz7(proj_b))
    gemm_pipe<2><<<dim3(8, 32), 256, 65536>>>(zq, wpj, proj_b, pj, 1024, 1024);
    // 8: x1 = qz4(x) + pj
    add1_kernel<<<4096, 256>>>(x, pj, x1);
    // 9: hq = qz4(affine(x1, aff2))
    affine_bf16_kernel<<<4096, 256>>>(x1, aff2_w, aff2_b, hq);
    // 10-11: fc1
    quantw_kernel<<<4096, 256>>>(fc1_w, wf1);
    gemm_pipe<3><<<dim3(32, 32), 256, 65536>>>(hq, wf1, fc1_b, mid, 4096, 1024);
    // 12-13: fc2
    quantw_kernel<<<4096, 256>>>(fc2_w, wf2);
    gemm_pipe<2><<<dim3(8, 32), 256, 65536>>>(mid, wf2, fc2_b, f2, 1024, 4096);
    // 14: out = qz4(x1) + f2
    add2_kernel<<<4096, 256>>>(x1, f2, out);
}